// round 6
// baseline (speedup 1.0000x reference)
#include <cuda_runtime.h>
#include <cstdint>

// Problem constants
constexpr int Tt = 1024;   // timesteps
constexpr int Bb = 128;    // batch
constexpr int Ii = 256;    // input dim
constexpr int Hh = 512;    // hidden dim
constexpr long long TBH = (long long)Tt * Bb * Hh;   // output region size

using ull = unsigned long long;

// -------------------------------------------------------------------------
// packed fp32 helpers (exact fp32 semantics)
// -------------------------------------------------------------------------
__device__ __forceinline__ void ffma2(ull& d, ull a, ull b) {
    asm("fma.rn.f32x2 %0, %1, %2, %0;" : "+l"(d) : "l"(a), "l"(b));
}
__device__ __forceinline__ ull dup2(float x) {
    ull r;
    asm("mov.b64 %0, {%1, %1};" : "=l"(r) : "f"(x));
    return r;
}
__device__ __forceinline__ float2 unpk(ull v) {
    float2 r;
    asm("mov.b64 {%0, %1}, %2;" : "=f"(r.x), "=f"(r.y) : "l"(v));
    return r;
}

// accurate tanh that survives --use_fast_math
__device__ __forceinline__ float tanh_acc(float x) {
    float ax = fabsf(x);
    float e  = __expf(-2.0f * ax);
    float r  = (1.0f - e) / (1.0f + e);
    return copysignf(r, x);
}

// =========================================================================
// Kernel 1: xw = x @ Wi^T  into d_out[0 : T*B*H)   (unchanged)
// =========================================================================
__global__ void __launch_bounds__(256, 2)
xw_gemm_kernel(const float* __restrict__ x,
               const float* __restrict__ Wi,
               float* __restrict__ out)
{
    __shared__ float As[32][132];   // [k][m], padded
    __shared__ float Bs[32][132];   // [k][n], padded

    const int m0 = (blockIdx.x >> 2) * 128;
    const int n0 = (blockIdx.x & 3) * 128;
    const int tid = threadIdx.x;
    const int mt = tid >> 4;                  // 0..15 -> m rows mt*8..+7
    const int nt = tid & 15;                  // 0..15 -> n cols 4nt..+3, 64+4nt..+3

    ull acc2[8][4];
    #pragma unroll
    for (int i = 0; i < 8; i++)
        #pragma unroll
        for (int j = 0; j < 4; j++) acc2[i][j] = 0ULL;

    for (int k0 = 0; k0 < Ii; k0 += 32) {
        #pragma unroll
        for (int r = 0; r < 4; r++) {
            int f   = tid + r * 256;
            int row = f >> 3;
            int kq  = (f & 7) << 2;
            float4 va = *reinterpret_cast<const float4*>(
                &x[(size_t)(m0 + row) * Ii + k0 + kq]);
            As[kq + 0][row] = va.x; As[kq + 1][row] = va.y;
            As[kq + 2][row] = va.z; As[kq + 3][row] = va.w;
            float4 vb = *reinterpret_cast<const float4*>(
                &Wi[(size_t)(n0 + row) * Ii + k0 + kq]);
            Bs[kq + 0][row] = vb.x; Bs[kq + 1][row] = vb.y;
            Bs[kq + 2][row] = vb.z; Bs[kq + 3][row] = vb.w;
        }
        __syncthreads();

        #pragma unroll 4
        for (int kk = 0; kk < 32; kk++) {
            float4 av0 = *reinterpret_cast<const float4*>(&As[kk][mt * 8]);
            float4 av1 = *reinterpret_cast<const float4*>(&As[kk][mt * 8 + 4]);
            ulonglong2 b0 = *reinterpret_cast<const ulonglong2*>(&Bs[kk][nt * 4]);
            ulonglong2 b1 = *reinterpret_cast<const ulonglong2*>(&Bs[kk][64 + nt * 4]);
            float am[8] = {av0.x, av0.y, av0.z, av0.w, av1.x, av1.y, av1.z, av1.w};
            #pragma unroll
            for (int i = 0; i < 8; i++) {
                ull d = dup2(am[i]);
                ffma2(acc2[i][0], d, b0.x);
                ffma2(acc2[i][1], d, b0.y);
                ffma2(acc2[i][2], d, b1.x);
                ffma2(acc2[i][3], d, b1.y);
            }
        }
        __syncthreads();
    }

    #pragma unroll
    for (int i = 0; i < 8; i++) {
        float2 p0 = unpk(acc2[i][0]), p1 = unpk(acc2[i][1]);
        float2 p2 = unpk(acc2[i][2]), p3 = unpk(acc2[i][3]);
        size_t g = (size_t)(m0 + mt * 8 + i) * Hh + n0;
        *reinterpret_cast<float4*>(&out[g + nt * 4]) =
            make_float4(p0.x, p0.y, p1.x, p1.y);
        *reinterpret_cast<float4*>(&out[g + 64 + nt * 4]) =
            make_float4(p2.x, p2.y, p3.x, p3.y);
    }
}

// =========================================================================
// Kernel 2: recurrent scan, 512 threads / 16 warps, NO SPILLS by design.
//   16 clusters x 8 CTAs; cluster c owns batch rows [c*8, +8);
//   CTA rank r owns output columns [r*64, +64).
//   Thread (kg = tid>>6 in 0..7, j_l = tid&63) owns ONE j column's 64-k
//   weight slice: w2[32] k-packed f32x2 (64 regs). 8 accumulators (16 regs).
//   Inner loop: per q (4 k), process batch rows in TWO halves of 4 so only
//   4 hv ulonglong2 (16 regs) are live -> total ~116 regs < 128 cap.
//   Two warps share each kg (j_l halves); all lanes of a warp load the
//   same h address (broadcast LDS.128).
// =========================================================================
constexpr int H_S_PITCH = Hh + 4;         // 516 floats
constexpr int H_S_ELEMS = 8 * H_S_PITCH;  // 4128
constexpr int RED_ELEMS = 8 * 8 * 64;     // red[kg][b][j] = 4096

__global__ void __cluster_dims__(8, 1, 1) __launch_bounds__(512, 1)
rnn_scan_kernel(const float* __restrict__ Wh, float* __restrict__ out)
{
    __shared__ float h_s[H_S_ELEMS];
    __shared__ float red[RED_ELEMS];

    const int tid  = threadIdx.x;
    const int cid  = blockIdx.x >> 3;
    const int rank = blockIdx.x & 7;
    const int b0   = cid * 8;                // batch rows of this cluster
    const int j0   = rank * 64;              // output columns of this CTA

    const int kg  = tid >> 6;                // 0..7 : k range [kg*64, +64)
    const int j_l = tid & 63;                // 0..63: owned j column
    const int kbase = kg * 64;

    // ---- one-time: this thread's 64 Wh weights, k-packed f32x2 (64 regs)
    ull w2[32];
    {
        const ull* wr = reinterpret_cast<const ull*>(
            Wh + (size_t)(j0 + j_l) * Hh + kbase);
        #pragma unroll
        for (int kp = 0; kp < 32; kp++) w2[kp] = wr[kp];
    }

    // ---- h_{-1} = 0
    for (int i = tid; i < H_S_ELEMS; i += 512) h_s[i] = 0.0f;
    __syncthreads();

    // epilogue: one output per thread, o = tid = b_l*64 + j_le
    const int b_l  = tid >> 6;               // == kg numerically
    const int j_le = tid & 63;

    const float* hsrc = h_s + kbase;         // hoisted base for inner loads

    // prefetch xw for t=0
    float xw = out[((size_t)0 * Bb + b0 + b_l) * Hh + j0 + j_le];

    for (int t = 0; t < Tt; t++) {
        // ---- partial dot: acc[b] = sum_{k in kg range} h[b][k]*Wh[j][k]
        ull acc[8];
        #pragma unroll
        for (int b = 0; b < 8; b++) acc[b] = 0ULL;

        #pragma unroll
        for (int q = 0; q < 16; q++) {
            // half 0: batch rows 0..3 (4 broadcast LDS.128, 16 live regs)
            {
                ulonglong2 h0 = *reinterpret_cast<const ulonglong2*>(hsrc + 0 * H_S_PITCH + q * 4);
                ulonglong2 h1 = *reinterpret_cast<const ulonglong2*>(hsrc + 1 * H_S_PITCH + q * 4);
                ulonglong2 h2 = *reinterpret_cast<const ulonglong2*>(hsrc + 2 * H_S_PITCH + q * 4);
                ulonglong2 h3 = *reinterpret_cast<const ulonglong2*>(hsrc + 3 * H_S_PITCH + q * 4);
                ffma2(acc[0], h0.x, w2[2 * q]); ffma2(acc[0], h0.y, w2[2 * q + 1]);
                ffma2(acc[1], h1.x, w2[2 * q]); ffma2(acc[1], h1.y, w2[2 * q + 1]);
                ffma2(acc[2], h2.x, w2[2 * q]); ffma2(acc[2], h2.y, w2[2 * q + 1]);
                ffma2(acc[3], h3.x, w2[2 * q]); ffma2(acc[3], h3.y, w2[2 * q + 1]);
            }
            // half 1: batch rows 4..7
            {
                ulonglong2 h4 = *reinterpret_cast<const ulonglong2*>(hsrc + 4 * H_S_PITCH + q * 4);
                ulonglong2 h5 = *reinterpret_cast<const ulonglong2*>(hsrc + 5 * H_S_PITCH + q * 4);
                ulonglong2 h6 = *reinterpret_cast<const ulonglong2*>(hsrc + 6 * H_S_PITCH + q * 4);
                ulonglong2 h7 = *reinterpret_cast<const ulonglong2*>(hsrc + 7 * H_S_PITCH + q * 4);
                ffma2(acc[4], h4.x, w2[2 * q]); ffma2(acc[4], h4.y, w2[2 * q + 1]);
                ffma2(acc[5], h5.x, w2[2 * q]); ffma2(acc[5], h5.y, w2[2 * q + 1]);
                ffma2(acc[6], h6.x, w2[2 * q]); ffma2(acc[6], h6.y, w2[2 * q + 1]);
                ffma2(acc[7], h7.x, w2[2 * q]); ffma2(acc[7], h7.y, w2[2 * q + 1]);
            }
        }

        // ---- horizontal add + cross-kg reduction via smem
        #pragma unroll
        for (int b = 0; b < 8; b++) {
            float2 p = unpk(acc[b]);
            red[kg * 512 + b * 64 + j_l] = p.x + p.y;
        }
        __syncthreads();

        float s = 0.0f;
        #pragma unroll
        for (int g = 0; g < 8; g++) s += red[g * 512 + tid];

        float h = tanh_acc(xw + s);

        // write h_t over xw in d_out[t]
        out[((size_t)t * Bb + b0 + b_l) * Hh + j0 + j_le] = h;
        if (t == Tt - 1) {   // h_final tail
            out[TBH + (size_t)(b0 + b_l) * Hh + j0 + j_le] = h;
        }

        // prefetch next step's xw (overwritten next iteration)
        {
            int tn = (t + 1 < Tt) ? (t + 1) : (Tt - 1);
            xw = out[((size_t)tn * Bb + b0 + b_l) * Hh + j0 + j_le];
        }

        // ---- cluster barrier: release our h slice, acquire peers' slices
        asm volatile("barrier.cluster.arrive.aligned;" ::: "memory");
        asm volatile("barrier.cluster.wait.aligned;"   ::: "memory");

        // ---- reload full h_t for our 8 batch rows (16 KB from L2, skip L1)
        const float* hg = out + ((size_t)t * Bb + b0) * Hh;
        #pragma unroll
        for (int r = 0; r < 2; r++) {
            int f = tid + r * 512;           // float4 index 0..1023
            int b = f >> 7;
            int k = (f & 127) << 2;
            float4 v = __ldcg(reinterpret_cast<const float4*>(
                hg + (size_t)b * Hh + k));
            *reinterpret_cast<float4*>(h_s + b * H_S_PITCH + k) = v;
        }
        __syncthreads();
    }
}

// =========================================================================
// launcher
// =========================================================================
extern "C" void kernel_launch(void* const* d_in, const int* in_sizes, int n_in,
                              void* d_out, int out_size)
{
    const float* x  = (const float*)d_in[0];   // [T, B, I]
    const float* Wi = (const float*)d_in[1];   // [H, I]
    const float* Wh = (const float*)d_in[2];   // [H, H]
    float* out = (float*)d_out;

    (void)in_sizes; (void)n_in; (void)out_size;

    xw_gemm_kernel<<<(Tt * Bb / 128) * (Hh / 128), 256>>>(x, Wi, out);

    rnn_scan_kernel<<<128, 512>>>(Wh, out);
}

// round 7
// speedup vs baseline: 1.0787x; 1.0787x over previous
#include <cuda_runtime.h>
#include <cstdint>

// Problem constants
constexpr int Tt = 1024;   // timesteps
constexpr int Bb = 128;    // batch
constexpr int Ii = 256;    // input dim
constexpr int Hh = 512;    // hidden dim
constexpr long long TBH = (long long)Tt * Bb * Hh;   // output region size

using ull = unsigned long long;

// -------------------------------------------------------------------------
// packed fp32 helpers (exact fp32 semantics)
// -------------------------------------------------------------------------
__device__ __forceinline__ void ffma2(ull& d, ull a, ull b) {
    asm("fma.rn.f32x2 %0, %1, %2, %0;" : "+l"(d) : "l"(a), "l"(b));
}
__device__ __forceinline__ ull dup2(float x) {
    ull r;
    asm("mov.b64 %0, {%1, %1};" : "=l"(r) : "f"(x));
    return r;
}
__device__ __forceinline__ float2 unpk(ull v) {
    float2 r;
    asm("mov.b64 {%0, %1}, %2;" : "=f"(r.x), "=f"(r.y) : "l"(v));
    return r;
}

// accurate tanh that survives --use_fast_math
__device__ __forceinline__ float tanh_acc(float x) {
    float ax = fabsf(x);
    float e  = __expf(-2.0f * ax);
    float r  = (1.0f - e) / (1.0f + e);
    return copysignf(r, x);
}

// =========================================================================
// Kernel 1: xw = x @ Wi^T  into d_out[0 : T*B*H)   (unchanged)
// =========================================================================
__global__ void __launch_bounds__(256, 2)
xw_gemm_kernel(const float* __restrict__ x,
               const float* __restrict__ Wi,
               float* __restrict__ out)
{
    __shared__ float As[32][132];   // [k][m], padded
    __shared__ float Bs[32][132];   // [k][n], padded

    const int m0 = (blockIdx.x >> 2) * 128;
    const int n0 = (blockIdx.x & 3) * 128;
    const int tid = threadIdx.x;
    const int mt = tid >> 4;                  // 0..15 -> m rows mt*8..+7
    const int nt = tid & 15;                  // 0..15 -> n cols 4nt..+3, 64+4nt..+3

    ull acc2[8][4];
    #pragma unroll
    for (int i = 0; i < 8; i++)
        #pragma unroll
        for (int j = 0; j < 4; j++) acc2[i][j] = 0ULL;

    for (int k0 = 0; k0 < Ii; k0 += 32) {
        #pragma unroll
        for (int r = 0; r < 4; r++) {
            int f   = tid + r * 256;
            int row = f >> 3;
            int kq  = (f & 7) << 2;
            float4 va = *reinterpret_cast<const float4*>(
                &x[(size_t)(m0 + row) * Ii + k0 + kq]);
            As[kq + 0][row] = va.x; As[kq + 1][row] = va.y;
            As[kq + 2][row] = va.z; As[kq + 3][row] = va.w;
            float4 vb = *reinterpret_cast<const float4*>(
                &Wi[(size_t)(n0 + row) * Ii + k0 + kq]);
            Bs[kq + 0][row] = vb.x; Bs[kq + 1][row] = vb.y;
            Bs[kq + 2][row] = vb.z; Bs[kq + 3][row] = vb.w;
        }
        __syncthreads();

        #pragma unroll 4
        for (int kk = 0; kk < 32; kk++) {
            float4 av0 = *reinterpret_cast<const float4*>(&As[kk][mt * 8]);
            float4 av1 = *reinterpret_cast<const float4*>(&As[kk][mt * 8 + 4]);
            ulonglong2 b0 = *reinterpret_cast<const ulonglong2*>(&Bs[kk][nt * 4]);
            ulonglong2 b1 = *reinterpret_cast<const ulonglong2*>(&Bs[kk][64 + nt * 4]);
            float am[8] = {av0.x, av0.y, av0.z, av0.w, av1.x, av1.y, av1.z, av1.w};
            #pragma unroll
            for (int i = 0; i < 8; i++) {
                ull d = dup2(am[i]);
                ffma2(acc2[i][0], d, b0.x);
                ffma2(acc2[i][1], d, b0.y);
                ffma2(acc2[i][2], d, b1.x);
                ffma2(acc2[i][3], d, b1.y);
            }
        }
        __syncthreads();
    }

    #pragma unroll
    for (int i = 0; i < 8; i++) {
        float2 p0 = unpk(acc2[i][0]), p1 = unpk(acc2[i][1]);
        float2 p2 = unpk(acc2[i][2]), p3 = unpk(acc2[i][3]);
        size_t g = (size_t)(m0 + mt * 8 + i) * Hh + n0;
        *reinterpret_cast<float4*>(&out[g + nt * 4]) =
            make_float4(p0.x, p0.y, p1.x, p1.y);
        *reinterpret_cast<float4*>(&out[g + 64 + nt * 4]) =
            make_float4(p2.x, p2.y, p3.x, p3.y);
    }
}

// =========================================================================
// Kernel 2: recurrent scan — smem weights, 512 threads / 16 warps.
//   16 clusters x 8 CTAs; cluster c owns batch rows [c*8, +8);
//   CTA rank r owns output columns [r*64, +64).
//   Weights live in smem PRE-PAIRED over k:
//     w_s[kp][j] = ull( Wh[j0+j][2kp], Wh[j0+j][2kp+1] ),  kp = 0..255.
//   Warp = kg (16 groups, 32-k slice = 16 kp). Lane jt owns j pair
//   (2jt, 2jt+1); computes all 8 batch rows. Accumulators pack over k
//   (lanes = k-even/k-odd partials), 16 accs. Inner iter = 4 k:
//     2 w-LDS.128 (lane stride 16B, conflict-free 4-phase)
//     8 h-LDS.128 (warp-broadcast, 1 phase)
//     32 FFMA2, zero dup2.
//   ~90-110 regs -> no spill at 512-thread 128-reg cap; 4 warps/SMSP
//   to hide LDS latency. Cross-kg reduce via red[16][512].
// =========================================================================
constexpr int W_ULLS   = 256 * 64;                    // 16384 ulls = 131072 B
constexpr int H_S_PITCH = Hh + 4;                     // 516 floats
constexpr int H_S_ELEMS = 8 * H_S_PITCH;              // 4128 floats = 16512 B
constexpr int RED_ELEMS = 16 * 512;                   // 8192 floats = 32768 B
constexpr int SCAN_SMEM_BYTES =
    W_ULLS * 8 + H_S_ELEMS * 4 + RED_ELEMS * 4;       // 180352 B

__global__ void __cluster_dims__(8, 1, 1) __launch_bounds__(512, 1)
rnn_scan_kernel(const float* __restrict__ Wh, float* __restrict__ out)
{
    extern __shared__ char dynsmem[];
    ull*   w_s = reinterpret_cast<ull*>(dynsmem);                 // [256][64]
    float* h_s = reinterpret_cast<float*>(dynsmem + W_ULLS * 8);  // [8][516]
    float* red = h_s + H_S_ELEMS;                                 // [16][512]

    const int tid  = threadIdx.x;
    const int cid  = blockIdx.x >> 3;
    const int rank = blockIdx.x & 7;
    const int b0   = cid * 8;                // batch rows of this cluster
    const int j0   = rank * 64;              // output columns of this CTA

    const int kg = tid >> 5;                 // warp id 0..15: kp slice [kg*16,+16)
    const int jt = tid & 31;                 // lane: j pair (2jt, 2jt+1)
    const int kp0 = kg * 16;

    // ---- one-time: fill w_s[kp][j] = k-paired ull of Wh[j0+j][2kp..2kp+1]
    for (int idx = tid; idx < W_ULLS; idx += 512) {
        int kp = idx >> 6;
        int j  = idx & 63;
        w_s[idx] = *reinterpret_cast<const ull*>(
            Wh + (size_t)(j0 + j) * Hh + 2 * kp);
    }
    // ---- h_{-1} = 0
    for (int i = tid; i < H_S_ELEMS; i += 512) h_s[i] = 0.0f;
    __syncthreads();

    // epilogue: one output per thread, o = tid = b_l*64 + j_le
    const int b_l  = tid >> 6;
    const int j_le = tid & 63;

    const ull*   wbase = w_s + (size_t)kp0 * 64 + 2 * jt;
    const float* hbase = h_s + 2 * kp0;      // float offset of this kg's k range

    // prefetch xw for t=0
    float xw = out[((size_t)0 * Bb + b0 + b_l) * Hh + j0 + j_le];

    for (int t = 0; t < Tt; t++) {
        // ---- partial dots: acc[b][jj] over k slice, packed (k even, k odd)
        ull acc[8][2];
        #pragma unroll
        for (int b = 0; b < 8; b++) { acc[b][0] = 0ULL; acc[b][1] = 0ULL; }

        #pragma unroll
        for (int it = 0; it < 8; it++) {     // 2 kp (= 4 k) per iter
            const ull* wrow = wbase + (size_t)(2 * it) * 64;
            ulonglong2 wv0 = *reinterpret_cast<const ulonglong2*>(wrow);       // kp
            ulonglong2 wv1 = *reinterpret_cast<const ulonglong2*>(wrow + 64);  // kp+1
            #pragma unroll
            for (int b = 0; b < 8; b++) {
                // broadcast: 16B of h covering k = 4it .. 4it+3 of this slice
                ulonglong2 hv = *reinterpret_cast<const ulonglong2*>(
                    hbase + b * H_S_PITCH + 4 * it);
                ffma2(acc[b][0], hv.x, wv0.x);
                ffma2(acc[b][1], hv.x, wv0.y);
                ffma2(acc[b][0], hv.y, wv1.x);
                ffma2(acc[b][1], hv.y, wv1.y);
            }
        }

        // ---- horizontal add + cross-kg reduction via smem
        #pragma unroll
        for (int b = 0; b < 8; b++) {
            float2 p0 = unpk(acc[b][0]);
            float2 p1 = unpk(acc[b][1]);
            *reinterpret_cast<float2*>(red + kg * 512 + b * 64 + 2 * jt) =
                make_float2(p0.x + p0.y, p1.x + p1.y);
        }
        __syncthreads();

        float s = 0.0f;
        #pragma unroll
        for (int g = 0; g < 16; g++) s += red[g * 512 + tid];

        float h = tanh_acc(xw + s);

        // write h_t over xw in d_out[t]
        out[((size_t)t * Bb + b0 + b_l) * Hh + j0 + j_le] = h;
        if (t == Tt - 1) {   // h_final tail
            out[TBH + (size_t)(b0 + b_l) * Hh + j0 + j_le] = h;
        }

        // prefetch next step's xw (overwritten next iteration)
        {
            int tn = (t + 1 < Tt) ? (t + 1) : (Tt - 1);
            xw = out[((size_t)tn * Bb + b0 + b_l) * Hh + j0 + j_le];
        }

        // ---- cluster barrier: release our h slice, acquire peers' slices
        asm volatile("barrier.cluster.arrive.aligned;" ::: "memory");
        asm volatile("barrier.cluster.wait.aligned;"   ::: "memory");

        // ---- reload full h_t for our 8 batch rows (16 KB from L2, skip L1)
        const float* hg = out + ((size_t)t * Bb + b0) * Hh;
        #pragma unroll
        for (int r = 0; r < 2; r++) {
            int f = tid + r * 512;           // float4 index 0..1023
            int b = f >> 7;
            int k = (f & 127) << 2;
            float4 v = __ldcg(reinterpret_cast<const float4*>(
                hg + (size_t)b * Hh + k));
            *reinterpret_cast<float4*>(h_s + b * H_S_PITCH + k) = v;
        }
        __syncthreads();
    }
}

// =========================================================================
// launcher
// =========================================================================
extern "C" void kernel_launch(void* const* d_in, const int* in_sizes, int n_in,
                              void* d_out, int out_size)
{
    const float* x  = (const float*)d_in[0];   // [T, B, I]
    const float* Wi = (const float*)d_in[1];   // [H, I]
    const float* Wh = (const float*)d_in[2];   // [H, H]
    float* out = (float*)d_out;

    (void)in_sizes; (void)n_in; (void)out_size;

    xw_gemm_kernel<<<(Tt * Bb / 128) * (Hh / 128), 256>>>(x, Wi, out);

    cudaFuncSetAttribute(rnn_scan_kernel,
                         cudaFuncAttributeMaxDynamicSharedMemorySize,
                         SCAN_SMEM_BYTES);
    rnn_scan_kernel<<<128, 512, SCAN_SMEM_BYTES>>>(Wh, out);
}

// round 8
// speedup vs baseline: 1.4394x; 1.3343x over previous
#include <cuda_runtime.h>
#include <cstdint>

// Problem constants
constexpr int Tt = 1024;   // timesteps
constexpr int Bb = 128;    // batch
constexpr int Ii = 256;    // input dim
constexpr int Hh = 512;    // hidden dim
constexpr long long TBH = (long long)Tt * Bb * Hh;   // output region size

using ull = unsigned long long;

// -------------------------------------------------------------------------
// packed fp32 helpers (exact fp32 semantics)
// -------------------------------------------------------------------------
__device__ __forceinline__ void ffma2(ull& d, ull a, ull b) {
    asm("fma.rn.f32x2 %0, %1, %2, %0;" : "+l"(d) : "l"(a), "l"(b));
}
__device__ __forceinline__ ull dup2(float x) {
    ull r;
    asm("mov.b64 %0, {%1, %1};" : "=l"(r) : "f"(x));
    return r;
}
__device__ __forceinline__ float2 unpk(ull v) {
    float2 r;
    asm("mov.b64 {%0, %1}, %2;" : "=f"(r.x), "=f"(r.y) : "l"(v));
    return r;
}

// accurate tanh that survives --use_fast_math
__device__ __forceinline__ float tanh_acc(float x) {
    float ax = fabsf(x);
    float e  = __expf(-2.0f * ax);
    float r  = (1.0f - e) / (1.0f + e);
    return copysignf(r, x);
}

// -------------------------------------------------------------------------
// cluster / mbarrier / bulk-copy primitives
// -------------------------------------------------------------------------
__device__ __forceinline__ uint32_t smem_u32(const void* p) {
    uint32_t a;
    asm("{ .reg .u64 t; cvta.to.shared.u64 t, %1; cvt.u32.u64 %0, t; }"
        : "=r"(a) : "l"(p));
    return a;
}
__device__ __forceinline__ uint32_t mapa_u32(uint32_t addr, uint32_t rank) {
    uint32_t r;
    asm("mapa.shared::cluster.u32 %0, %1, %2;" : "=r"(r) : "r"(addr), "r"(rank));
    return r;
}
__device__ __forceinline__ void mbar_init(uint32_t mbar, uint32_t count) {
    asm volatile("mbarrier.init.shared.b64 [%0], %1;" :: "r"(mbar), "r"(count) : "memory");
}
__device__ __forceinline__ void mbar_expect_tx(uint32_t mbar, uint32_t bytes) {
    asm volatile("mbarrier.arrive.expect_tx.shared.b64 _, [%0], %1;"
                 :: "r"(mbar), "r"(bytes) : "memory");
}
__device__ __forceinline__ void mbar_wait(uint32_t mbar, uint32_t parity) {
    asm volatile(
        "{\n\t"
        ".reg .pred P;\n"
        "WAIT_%=:\n\t"
        "mbarrier.try_wait.parity.acquire.cta.shared::cta.b64 P, [%0], %1, 0x989680;\n\t"
        "@!P bra WAIT_%=;\n\t"
        "}"
        :: "r"(mbar), "r"(parity) : "memory");
}
// CTA->CTA (cluster) bulk smem copy with complete_tx on the DEST mbarrier
__device__ __forceinline__ void bulk_s2s(uint32_t dst_cluster, uint32_t src_cta,
                                         uint32_t bytes, uint32_t mbar_cluster) {
    asm volatile(
        "cp.async.bulk.shared::cluster.shared::cta.mbarrier::complete_tx::bytes "
        "[%0], [%1], %2, [%3];"
        :: "r"(dst_cluster), "r"(src_cta), "r"(bytes), "r"(mbar_cluster) : "memory");
}
__device__ __forceinline__ void fence_proxy_async_cta() {
    asm volatile("fence.proxy.async.shared::cta;" ::: "memory");
}

// =========================================================================
// Kernel 1: xw = x @ Wi^T  into d_out[0 : T*B*H)   (unchanged)
// =========================================================================
__global__ void __launch_bounds__(256, 2)
xw_gemm_kernel(const float* __restrict__ x,
               const float* __restrict__ Wi,
               float* __restrict__ out)
{
    __shared__ float As[32][132];   // [k][m], padded
    __shared__ float Bs[32][132];   // [k][n], padded

    const int m0 = (blockIdx.x >> 2) * 128;
    const int n0 = (blockIdx.x & 3) * 128;
    const int tid = threadIdx.x;
    const int mt = tid >> 4;
    const int nt = tid & 15;

    ull acc2[8][4];
    #pragma unroll
    for (int i = 0; i < 8; i++)
        #pragma unroll
        for (int j = 0; j < 4; j++) acc2[i][j] = 0ULL;

    for (int k0 = 0; k0 < Ii; k0 += 32) {
        #pragma unroll
        for (int r = 0; r < 4; r++) {
            int f   = tid + r * 256;
            int row = f >> 3;
            int kq  = (f & 7) << 2;
            float4 va = *reinterpret_cast<const float4*>(
                &x[(size_t)(m0 + row) * Ii + k0 + kq]);
            As[kq + 0][row] = va.x; As[kq + 1][row] = va.y;
            As[kq + 2][row] = va.z; As[kq + 3][row] = va.w;
            float4 vb = *reinterpret_cast<const float4*>(
                &Wi[(size_t)(n0 + row) * Ii + k0 + kq]);
            Bs[kq + 0][row] = vb.x; Bs[kq + 1][row] = vb.y;
            Bs[kq + 2][row] = vb.z; Bs[kq + 3][row] = vb.w;
        }
        __syncthreads();

        #pragma unroll 4
        for (int kk = 0; kk < 32; kk++) {
            float4 av0 = *reinterpret_cast<const float4*>(&As[kk][mt * 8]);
            float4 av1 = *reinterpret_cast<const float4*>(&As[kk][mt * 8 + 4]);
            ulonglong2 b0 = *reinterpret_cast<const ulonglong2*>(&Bs[kk][nt * 4]);
            ulonglong2 b1 = *reinterpret_cast<const ulonglong2*>(&Bs[kk][64 + nt * 4]);
            float am[8] = {av0.x, av0.y, av0.z, av0.w, av1.x, av1.y, av1.z, av1.w};
            #pragma unroll
            for (int i = 0; i < 8; i++) {
                ull d = dup2(am[i]);
                ffma2(acc2[i][0], d, b0.x);
                ffma2(acc2[i][1], d, b0.y);
                ffma2(acc2[i][2], d, b1.x);
                ffma2(acc2[i][3], d, b1.y);
            }
        }
        __syncthreads();
    }

    #pragma unroll
    for (int i = 0; i < 8; i++) {
        float2 p0 = unpk(acc2[i][0]), p1 = unpk(acc2[i][1]);
        float2 p2 = unpk(acc2[i][2]), p3 = unpk(acc2[i][3]);
        size_t g = (size_t)(m0 + mt * 8 + i) * Hh + n0;
        *reinterpret_cast<float4*>(&out[g + nt * 4]) =
            make_float4(p0.x, p0.y, p1.x, p1.y);
        *reinterpret_cast<float4*>(&out[g + 64 + nt * 4]) =
            make_float4(p2.x, p2.y, p3.x, p3.y);
    }
}

// =========================================================================
// Kernel 2: recurrent scan with DSMEM exchange (no cluster.sync in loop).
//   16 clusters x 8 CTAs; cluster c owns batch rows [c*8, +8);
//   CTA rank r owns output columns [r*64, +64). R3 compute core:
//   thread (kg = warp 0..7, jg = lane 0..31) owns Wh[j0+jg][kg*64..+64)
//   and Wh[j0+jg+32][...] as k-packed f32x2 register pairs.
//
//   h lives in double-buffered smem: buf[p][src_rank][b][jl] (16 KB each);
//   step t reads buf[t&1]. After reduce+tanh, h slice goes to a staging
//   buffer; one thread bulk-copies it into ALL 8 CTAs' buf[(t+1)&1] with
//   complete_tx on each destination's single mbarrier (expect 16 KB/step).
//   The mbarrier IS the cluster rendezvous: no cluster.sync, no L2 trip.
// =========================================================================
constexpr int BUF_FLOATS = 4096;                    // [8 src][8 b][64 j]
constexpr int BUF_BYTES  = BUF_FLOATS * 4;          // 16384
constexpr int RED_FLOATS = 4096;                    // [8 kg][8 b][64 j]
constexpr int STG_FLOATS = 512;                     // [8 b][64 j]
constexpr int OFF_BUF  = 0;                               // 2 x 16384
constexpr int OFF_RED  = 2 * BUF_BYTES;                   // 16384
constexpr int OFF_STG  = OFF_RED + RED_FLOATS * 4;        // 2 x 2048
constexpr int OFF_MBAR = OFF_STG + 2 * STG_FLOATS * 4;    // 8 B
constexpr int SCAN_SMEM_BYTES = OFF_MBAR + 16;            // 53264 -> pad

__global__ void __cluster_dims__(8, 1, 1) __launch_bounds__(256, 1)
rnn_scan_kernel(const float* __restrict__ Wh, float* __restrict__ out)
{
    extern __shared__ char dynsmem[];
    float* buf = reinterpret_cast<float*>(dynsmem + OFF_BUF);   // [2][4096]
    float* red = reinterpret_cast<float*>(dynsmem + OFF_RED);   // [4096]
    float* stg = reinterpret_cast<float*>(dynsmem + OFF_STG);   // [2][512]

    const uint32_t buf_a  = smem_u32(dynsmem + OFF_BUF);
    const uint32_t stg_a  = smem_u32(dynsmem + OFF_STG);
    const uint32_t mbar_a = smem_u32(dynsmem + OFF_MBAR);

    const int tid  = threadIdx.x;
    const int cid  = blockIdx.x >> 3;
    const int rank = blockIdx.x & 7;
    const int b0   = cid * 8;                // batch rows of this cluster
    const int j0   = rank * 64;              // output columns of this CTA

    const int kg = tid >> 5;                 // warp id: k range [kg*64, +64)
    const int jg = tid & 31;                 // lane: j cols j0+jg, j0+jg+32

    // ---- one-time: this thread's 128 Wh weights, k-packed f32x2 (regs)
    ull w2a[32], w2b[32];
    {
        const ull* wr0 = reinterpret_cast<const ull*>(
            Wh + (size_t)(j0 + jg) * Hh + kg * 64);
        const ull* wr1 = reinterpret_cast<const ull*>(
            Wh + (size_t)(j0 + jg + 32) * Hh + kg * 64);
        #pragma unroll
        for (int kp = 0; kp < 32; kp++) {
            w2a[kp] = wr0[kp];
            w2b[kp] = wr1[kp];
        }
    }

    // ---- init: buf[0] = h_{-1} = 0; single mbarrier count=1
    for (int i = tid; i < BUF_FLOATS; i += 256) buf[i] = 0.0f;
    if (tid == 0) mbar_init(mbar_a, 1);
    __syncthreads();
    // mbarriers + zeroed bufs must be cluster-visible before any peer copy
    asm volatile("barrier.cluster.arrive.aligned;" ::: "memory");
    asm volatile("barrier.cluster.wait.aligned;"   ::: "memory");

    // epilogue output assignment (2 outputs per thread): o = b_l*64 + j_l
    const int o0 = tid;
    const int o1 = tid + 256;
    const int b_l0 = o0 >> 6, j_l0 = o0 & 63;
    const int b_l1 = o1 >> 6, j_l1 = o1 & 63;

    // prefetch xw for t=0
    float xw0 = out[((size_t)0 * Bb + b0 + b_l0) * Hh + j0 + j_l0];
    float xw1 = out[((size_t)0 * Bb + b0 + b_l1) * Hh + j0 + j_l1];

    for (int t = 0; t < Tt; t++) {
        // ---- wait for this step's h (16 KB from 8 peers) — t=0 uses zeros
        if (t > 0) mbar_wait(mbar_a, (t - 1) & 1);
        // arm the barrier for NEXT step's incoming copies (sources are at
        // least one compute-phase behind; no expect/complete race)
        if (tid == 0 && t + 1 < Tt) mbar_expect_tx(mbar_a, 8 * 2048);

        const float* bufR = buf + (t & 1) * BUF_FLOATS + kg * 512;

        // ---- partial dot products (R3 core), f32x2 packed over k
        ull acc[8][2];
        #pragma unroll
        for (int b = 0; b < 8; b++) { acc[b][0] = 0ULL; acc[b][1] = 0ULL; }

        #pragma unroll
        for (int q = 0; q < 16; q++) {
            #pragma unroll
            for (int b = 0; b < 8; b++) {
                // broadcast: all 32 lanes read the same 16 bytes
                ulonglong2 hv = *reinterpret_cast<const ulonglong2*>(
                    bufR + b * 64 + q * 4);
                ffma2(acc[b][0], hv.x, w2a[2 * q]);
                ffma2(acc[b][1], hv.x, w2b[2 * q]);
                ffma2(acc[b][0], hv.y, w2a[2 * q + 1]);
                ffma2(acc[b][1], hv.y, w2b[2 * q + 1]);
            }
        }

        // ---- horizontal add + cross-warp (kg) reduction via smem
        #pragma unroll
        for (int b = 0; b < 8; b++) {
            float2 p0 = unpk(acc[b][0]);
            float2 p1 = unpk(acc[b][1]);
            red[kg * 512 + b * 64 + jg]      = p0.x + p0.y;
            red[kg * 512 + b * 64 + jg + 32] = p1.x + p1.y;
        }
        __syncthreads();

        float s0 = 0.0f, s1 = 0.0f;
        #pragma unroll
        for (int g = 0; g < 8; g++) {
            s0 += red[g * 512 + o0];
            s1 += red[g * 512 + o1];
        }

        float h0 = tanh_acc(xw0 + s0);
        float h1 = tanh_acc(xw1 + s1);

        // stage h slice for the DSMEM broadcast
        float* sg = stg + (t & 1) * STG_FLOATS;
        sg[o0] = h0;
        sg[o1] = h1;

        // write h_t over xw in d_out[t]  (fire-and-forget)
        out[((size_t)t * Bb + b0 + b_l0) * Hh + j0 + j_l0] = h0;
        out[((size_t)t * Bb + b0 + b_l1) * Hh + j0 + j_l1] = h1;
        if (t == Tt - 1) {   // h_final tail
            out[TBH + (size_t)(b0 + b_l0) * Hh + j0 + j_l0] = h0;
            out[TBH + (size_t)(b0 + b_l1) * Hh + j0 + j_l1] = h1;
        }

        // prefetch next step's xw
        {
            int tn = (t + 1 < Tt) ? (t + 1) : (Tt - 1);
            xw0 = out[((size_t)tn * Bb + b0 + b_l0) * Hh + j0 + j_l0];
            xw1 = out[((size_t)tn * Bb + b0 + b_l1) * Hh + j0 + j_l1];
        }

        __syncthreads();   // staging complete (also fences red reuse)

        // ---- broadcast my 2 KB slice into all 8 CTAs' buf[(t+1)&1]
        if (tid == 0 && t + 1 < Tt) {
            fence_proxy_async_cta();   // order generic STS before async reads
            uint32_t src = stg_a + (t & 1) * (STG_FLOATS * 4);
            uint32_t dst_local =
                buf_a + ((t + 1) & 1) * BUF_BYTES + rank * 2048;
            #pragma unroll
            for (uint32_t r = 0; r < 8; r++) {
                bulk_s2s(mapa_u32(dst_local, r), src, 2048,
                         mapa_u32(mbar_a, r));
            }
        }
    }

    // exit safety: no CTA leaves while peers might still target its smem
    asm volatile("barrier.cluster.arrive.aligned;" ::: "memory");
    asm volatile("barrier.cluster.wait.aligned;"   ::: "memory");
}

// =========================================================================
// launcher
// =========================================================================
extern "C" void kernel_launch(void* const* d_in, const int* in_sizes, int n_in,
                              void* d_out, int out_size)
{
    const float* x  = (const float*)d_in[0];   // [T, B, I]
    const float* Wi = (const float*)d_in[1];   // [H, I]
    const float* Wh = (const float*)d_in[2];   // [H, H]
    float* out = (float*)d_out;

    (void)in_sizes; (void)n_in; (void)out_size;

    xw_gemm_kernel<<<(Tt * Bb / 128) * (Hh / 128), 256>>>(x, Wi, out);

    cudaFuncSetAttribute(rnn_scan_kernel,
                         cudaFuncAttributeMaxDynamicSharedMemorySize,
                         SCAN_SMEM_BYTES);
    rnn_scan_kernel<<<128, 256, SCAN_SMEM_BYTES>>>(Wh, out);
}